// round 10
// baseline (speedup 1.0000x reference)
#include <cuda_runtime.h>

namespace {
constexpr int B  = 2;
constexpr int C  = 32;
constexpr int H  = 192;
constexpr int W  = 256;
constexpr int JH = 12;
constexpr int JW = 16;
constexpr int J  = JH * JW;      // 192
constexpr int N  = H * W;        // 49152
constexpr int HW = H * W;
constexpr int NITER = 10;
constexpr int SLOTS = NITER + 1; // slot 0 = init, slots 1..10 = iteration results
constexpr int PITCH = 260;       // 260*4B = 16B-aligned rows; LDS.128 conflict-free
constexpr int NB = B * J;        // 384 blocks; co-resident (4 CTAs/SM by smem/regs)
}

// Persistent scratch (device globals; no allocation allowed)
__device__ float    g_num[SLOTS][B * J * C];
__device__ float    g_den[SLOTS][B * J];
__device__ unsigned g_flag[SLOTS][B * J];

// ---------------------------------------------------------------------------
// Packed f32x2 helpers (Blackwell packed FP32: 2 FMAs per instruction)
// ---------------------------------------------------------------------------
__device__ __forceinline__ void ffma2(unsigned long long& d,
                                      unsigned long long a, unsigned long long b) {
    asm("fma.rn.f32x2 %0, %1, %2, %0;" : "+l"(d) : "l"(a), "l"(b));
}
__device__ __forceinline__ float f2sum(unsigned long long v) {
    float lo, hi;
    asm("mov.b64 {%0, %1}, %2;" : "=f"(lo), "=f"(hi) : "l"(v));
    return lo + hi;
}
__device__ __forceinline__ void f2unpack(unsigned long long v, float& lo, float& hi) {
    asm("mov.b64 {%0, %1}, %2;" : "=f"(lo), "=f"(hi) : "l"(v));
}
__device__ __forceinline__ unsigned long long f2pack(float lo, float hi) {
    unsigned long long r;
    asm("mov.b64 %0, {%1, %2};" : "=l"(r) : "f"(lo), "f"(hi));
    return r;
}

// Fire-and-forget global reductions (no return value -> no round-trip stall)
__device__ __forceinline__ void red_add_f32(float* p, float v) {
    asm volatile("red.relaxed.gpu.global.add.f32 [%0], %1;" :: "l"(p), "f"(v) : "memory");
}
__device__ __forceinline__ void red_add_release_u32(unsigned* p, unsigned v) {
    asm volatile("red.release.gpu.global.add.u32 [%0], %1;" :: "l"(p), "r"(v) : "memory");
}

// ---------------------------------------------------------------------------
// Reset the dataflow flags each replay (kernel boundary orders it vs k_fused).
// ---------------------------------------------------------------------------
__global__ void k_reset() {
    int i = blockIdx.x * blockDim.x + threadIdx.x;
    if (i < SLOTS * B * J) (&g_flag[0][0])[i] = 0u;
}

// Tight acquire poll (no sleep: discovery latency is on the critical path;
// poll period is naturally throttled by the L2 round trip)
__device__ __forceinline__ void poll_flag(const unsigned* p, unsigned expect) {
    unsigned v;
    do {
        asm volatile("ld.acquire.gpu.u32 %0, [%1];" : "=r"(v) : "l"(p) : "memory");
    } while (v < expect);
}

// ---------------------------------------------------------------------------
// Fully fused SSN: init + 10 iterations + final outputs, one persistent kernel.
// One CTA per (b, cell); 256 threads. Cross-cell sync via per-cell flags with
// release-reduction publish (contributors = 8 warps per neighboring block).
// ---------------------------------------------------------------------------
__global__ __launch_bounds__(256, 4) void k_fused(const float* __restrict__ feats,
                                                  float* __restrict__ gamma_out,
                                                  float* __restrict__ recon_out) {
    __shared__ __align__(16) float s_sh[9][C];          // neighbor spix / later fm
    __shared__ float sn_sh[9];
    __shared__ int   cell_sh[9];
    __shared__ int   expect_sh[9];
    __shared__ __align__(16) float pix_sh[C * PITCH];
    __shared__ __align__(16) float aff_sh[9][256];

    int blk = blockIdx.x;
    int b = blk / J, j = blk % J;
    int jy = j / JW, jx = j % JW;
    int bJ = b * J;
    int t = threadIdx.x;
    int wk = t >> 5, lane = t & 31;

    // neighbor table + expected contributor counts (static)
    if (t < 9) {
        int dy = t / 3 - 1, dx = t % 3 - 1;
        int ny = jy + dy, nx = jx + dx;
        int nc = (ny >= 0 && ny < JH && nx >= 0 && nx < JW) ? ny * JW + nx : -1;
        cell_sh[t] = nc;
        int ex = 0;
        if (nc >= 0) {
            int cy = 3 - (ny == 0) - (ny == JH - 1);
            int cx = 3 - (nx == 0) - (nx == JW - 1);
            ex = cy * cx;
        }
        expect_sh[t] = ex;
    }

    // load pixel features ONCE into smem; compute |f|^2 (fn persists, 1 reg)
    int py = t >> 4, px = t & 15;
    int y = jy * 16 + py, x = jx * 16 + px;
    int n = y * W + x;
    const float* fp = feats + (size_t)b * C * HW + n;
    float fn;
    {
        unsigned long long fn2 = 0ull;
        #pragma unroll
        for (int i = 0; i < 16; i++) {
            float lo = fp[(2 * i) * HW];
            float hi = fp[(2 * i + 1) * HW];
            pix_sh[(2 * i) * PITCH + t]     = lo;
            pix_sh[(2 * i + 1) * PITCH + t] = hi;
            unsigned long long v = f2pack(lo, hi);
            ffma2(fn2, v, v);
        }
        fn = f2sum(fn2);
    }

    // zero own cell's slots 1..10; write slot-0 den
    if (t < C) {
        #pragma unroll
        for (int s = 1; s < SLOTS; s++) g_num[s][(bJ + j) * C + t] = 0.0f;
    }
    if (t == C) {
        #pragma unroll
        for (int s = 1; s < SLOTS; s++) g_den[s][bJ + j] = 0.0f;
        g_den[0][bJ + j] = 256.0f;   // so num/(den+eps) == cell mean exactly
    }
    __syncthreads();   // pix_sh + tables ready

    // slot-0 num = per-channel sum over own 16x16 cell (warp slices -> tree)
    {
        const float* pr = &pix_sh[lane * PITCH + wk * 32];
        float ms = 0.0f;
        #pragma unroll
        for (int i = 0; i < 32; i += 4) {
            float4 v = *(const float4*)&pr[i];
            ms += (v.x + v.y) + (v.z + v.w);
        }
        ((float*)aff_sh)[wk * 32 + lane] = ms;
        __syncthreads();
        if (wk == 0) {
            float s = 0.0f;
            #pragma unroll
            for (int w2 = 0; w2 < 8; w2++) s += ((float*)aff_sh)[w2 * 32 + lane];
            g_num[0][(bJ + j) * C + lane] = s;
        }
    }
    __threadfence();           // init stores visible before the (single) slot-0 post
    __syncthreads();
    if (t == 0) atomicAdd(&g_flag[0][bJ + j], 1u);   // publish slot 0 (expect 1)

    float a[9];               // own-pixel affinities (persist to finale)

    for (int it = 0; it < NITER; it++) {
        // ---- phase 0: wait for + load neighbor spix from slot `it` ----
        for (int k = wk; k < 9; k += 8) {
            int nc = cell_sh[k];
            float sv = 0.0f;
            if (nc >= 0) {
                int idx = bJ + nc;
                unsigned ex = (it == 0) ? 1u : (unsigned)(expect_sh[k] * 8);
                poll_flag(&g_flag[it][idx], ex);
                sv = __ldcg(&g_num[it][idx * C + lane]) /
                     (__ldcg(&g_den[it][idx]) + 1e-16f);
            }
            s_sh[k][lane] = sv;
            float sq = sv * sv;
            #pragma unroll
            for (int o = 16; o; o >>= 1) sq += __shfl_xor_sync(0xffffffffu, sq, o);
            if (lane == 0) sn_sh[k] = sq;
        }
        __syncthreads();

        // ---- phase 1: distances (f32x2 FMA; f repacked from smem) + softmax ----
        unsigned long long d2[9];
        #pragma unroll
        for (int k = 0; k < 9; k++) d2[k] = 0ull;
        #pragma unroll
        for (int c4 = 0; c4 < 8; c4++) {
            float fa = pix_sh[(4 * c4 + 0) * PITCH + t];
            float fb = pix_sh[(4 * c4 + 1) * PITCH + t];
            float fc = pix_sh[(4 * c4 + 2) * PITCH + t];
            float fd = pix_sh[(4 * c4 + 3) * PITCH + t];
            unsigned long long fx = f2pack(fa, fb);
            unsigned long long fy = f2pack(fc, fd);
            #pragma unroll
            for (int k = 0; k < 9; k++) {
                ulonglong2 sv = ((const ulonglong2*)s_sh[k])[c4];
                ffma2(d2[k], fx, sv.x);
                ffma2(d2[k], fy, sv.y);
            }
        }
        float dist[9];
        #pragma unroll
        for (int k = 0; k < 9; k++)
            dist[k] = fn - 2.0f * f2sum(d2[k]) + sn_sh[k];

        float m = 3.0e38f;
        #pragma unroll
        for (int k = 0; k < 9; k++)
            if (cell_sh[k] >= 0) m = fminf(m, dist[k]);
        float sum = 0.0f;
        #pragma unroll
        for (int k = 0; k < 9; k++) {
            a[k] = (cell_sh[k] >= 0) ? __expf(m - dist[k]) : 0.0f;
            sum += a[k];
        }
        float inv = 1.0f / sum;
        #pragma unroll
        for (int k = 0; k < 9; k++) {
            a[k] *= inv;
            aff_sh[k][t] = a[k];
        }
        __syncthreads();

        // ---- phase 2: warp-slice accumulation + direct fire-and-forget reds ----
        unsigned long long acc2[9];
        #pragma unroll
        for (int k = 0; k < 9; k++) acc2[k] = 0ull;
        {
            int p0 = wk * 32;
            const float* pr = &pix_sh[lane * PITCH + p0];
            #pragma unroll
            for (int i = 0; i < 32; i += 4) {
                ulonglong2 pv = *(const ulonglong2*)&pr[i];
                #pragma unroll
                for (int k = 0; k < 9; k++) {
                    ulonglong2 av = *(const ulonglong2*)&aff_sh[k][p0 + i];  // bcast
                    ffma2(acc2[k], av.x, pv.x);
                    ffma2(acc2[k], av.y, pv.y);
                }
            }
        }
        // num: each warp posts its slice contribution for all 9 neighbors
        #pragma unroll
        for (int k = 0; k < 9; k++) {
            int nc = cell_sh[k];
            if (nc >= 0)
                red_add_f32(&g_num[it + 1][(bJ + nc) * C + lane], f2sum(acc2[k]));
        }
        // den: warp wk handles k = wk (and k=8 for warp 0)
        for (int k = wk; k < 9; k += 8) {
            int nc = cell_sh[k];
            if (nc >= 0) {
                float d = 0.0f;
                #pragma unroll
                for (int i2 = 0; i2 < 8; i2++) d += aff_sh[k][lane + (i2 << 5)];
                #pragma unroll
                for (int o = 16; o; o >>= 1) d += __shfl_xor_sync(0xffffffffu, d, o);
                if (lane == 0) red_add_f32(&g_den[it + 1][bJ + nc], d);
            }
        }
        // publish: syncwarp orders all lanes' reds; lane 0 release-posts flags
        __syncwarp();
        if (lane == 0) {
            #pragma unroll
            for (int k = 0; k < 9; k++) {
                int nc = cell_sh[k];
                if (nc >= 0) red_add_release_u32(&g_flag[it + 1][bJ + nc], 1u);
            }
        }
        __syncthreads();   // aff_sh reads done before next iteration overwrites
    }

    // =======================================================================
    // Finale: gamma first (reads aff_sh, already synced), then fm + recon.
    // =======================================================================
    const float* aff2 = &aff_sh[0][0];
    {
        int q = t & 63, jr = t >> 6;
        int r = q >> 2, colq = q & 3;
        size_t rowoff = (size_t)(jy * 16 + r) * W + jx * 16 + colq * 4;
        #pragma unroll 4
        for (int i = 0; i < 48; i++) {
            int jv  = jr + (i << 2);
            int jjy = jv >> 4, jjx = jv & 15;
            int ddy = jjy - jy, ddx = jjx - jx;
            float4 v = make_float4(0.f, 0.f, 0.f, 0.f);
            if (ddy >= -1 && ddy <= 1 && ddx >= -1 && ddx <= 1) {
                int k = (ddy + 1) * 3 + (ddx + 1);
                v = *(const float4*)&aff2[k * 256 + r * 16 + colq * 4];
            }
            __stcs((float4*)&gamma_out[((size_t)(bJ + jv)) * N + rowoff], v);
        }
    }

    // fm = num[10]/(den[10]+1e-6), gated on slot-10 flags (8 posts/contributor)
    for (int k = wk; k < 9; k += 8) {
        int nc = cell_sh[k];
        float fv = 0.0f;
        if (nc >= 0) {
            int idx = bJ + nc;
            poll_flag(&g_flag[NITER][idx], (unsigned)(expect_sh[k] * 8));
            fv = __ldcg(&g_num[NITER][idx * C + lane]) /
                 (__ldcg(&g_den[NITER][idx]) + 1e-6f);
        }
        s_sh[k][lane] = fv;
    }
    __syncthreads();

    // recon[b,c,n] = sum_k a[k] * fm[cell_k][c]   (f32x2)
    unsigned long long rec2[16];
    #pragma unroll
    for (int i = 0; i < 16; i++) rec2[i] = 0ull;
    #pragma unroll
    for (int k = 0; k < 9; k++) {
        unsigned long long ak2 = f2pack(a[k], a[k]);
        const ulonglong2* s2 = (const ulonglong2*)s_sh[k];
        #pragma unroll
        for (int c4 = 0; c4 < 8; c4++) {
            ulonglong2 sv = s2[c4];
            ffma2(rec2[2 * c4],     ak2, sv.x);
            ffma2(rec2[2 * c4 + 1], ak2, sv.y);
        }
    }
    #pragma unroll
    for (int i = 0; i < 16; i++) {
        float lo, hi;
        f2unpack(rec2[i], lo, hi);
        __stcs(&recon_out[((size_t)(b * C + 2 * i) * H + y) * W + x], lo);
        __stcs(&recon_out[((size_t)(b * C + 2 * i + 1) * H + y) * W + x], hi);
    }
}

// ---------------------------------------------------------------------------
extern "C" void kernel_launch(void* const* d_in, const int* in_sizes, int n_in,
                              void* d_out, int out_size) {
    (void)in_sizes; (void)n_in; (void)out_size;
    const float* feats = (const float*)d_in[0];
    float* gamma = (float*)d_out;
    float* recon = gamma + (size_t)B * J * N;

    k_reset<<<(SLOTS * B * J + 255) / 256, 256>>>();
    k_fused<<<NB, 256>>>(feats, gamma, recon);
}

// round 11
// speedup vs baseline: 1.7932x; 1.7932x over previous
#include <cuda_runtime.h>

namespace {
constexpr int B  = 2;
constexpr int C  = 32;
constexpr int H  = 192;
constexpr int W  = 256;
constexpr int JH = 12;
constexpr int JW = 16;
constexpr int J  = JH * JW;      // 192
constexpr int N  = H * W;        // 49152
constexpr int HW = H * W;
constexpr int NITER = 10;
constexpr int SLOTS = NITER + 1; // slot 0 = init, slots 1..10 = iteration results
constexpr int PITCH = 260;       // 260*4B = 16B-aligned rows; LDS.128 conflict-free
constexpr int NB = B * J;        // 384 blocks; co-resident
}

// Persistent scratch (device globals; no allocation allowed)
__device__ float    g_num[SLOTS][B * J * C];
__device__ float    g_den[SLOTS][B * J];
__device__ unsigned g_flag[SLOTS][B * J];

// ---------------------------------------------------------------------------
// Packed f32x2 helpers (Blackwell packed FP32: 2 FMAs per instruction)
// ---------------------------------------------------------------------------
__device__ __forceinline__ void ffma2(unsigned long long& d,
                                      unsigned long long a, unsigned long long b) {
    asm("fma.rn.f32x2 %0, %1, %2, %0;" : "+l"(d) : "l"(a), "l"(b));
}
__device__ __forceinline__ float f2sum(unsigned long long v) {
    float lo, hi;
    asm("mov.b64 {%0, %1}, %2;" : "=f"(lo), "=f"(hi) : "l"(v));
    return lo + hi;
}
__device__ __forceinline__ void f2unpack(unsigned long long v, float& lo, float& hi) {
    asm("mov.b64 {%0, %1}, %2;" : "=f"(lo), "=f"(hi) : "l"(v));
}
__device__ __forceinline__ unsigned long long f2pack(float lo, float hi) {
    unsigned long long r;
    asm("mov.b64 %0, {%1, %2};" : "=l"(r) : "f"(lo), "f"(hi));
    return r;
}

// ---------------------------------------------------------------------------
// Reset the dataflow flags each replay (kernel boundary orders it vs k_fused).
// ---------------------------------------------------------------------------
__global__ void k_reset() {
    int i = blockIdx.x * blockDim.x + threadIdx.x;
    if (i < SLOTS * B * J) (&g_flag[0][0])[i] = 0u;
}

// Joint acquire-poll of up to two flags (nanosleep-throttled; exits when both hit)
__device__ __forceinline__ void poll_flag2(const unsigned* p1, unsigned e1,
                                           const unsigned* p2, unsigned e2) {
    bool d1 = (p1 == nullptr), d2 = (p2 == nullptr);
    while (true) {
        if (!d1) {
            unsigned v;
            asm volatile("ld.acquire.gpu.u32 %0, [%1];" : "=r"(v) : "l"(p1) : "memory");
            d1 = (v >= e1);
        }
        if (!d2) {
            unsigned v;
            asm volatile("ld.acquire.gpu.u32 %0, [%1];" : "=r"(v) : "l"(p2) : "memory");
            d2 = (v >= e2);
        }
        if (d1 && d2) return;
        __nanosleep(64);
    }
}

// ---------------------------------------------------------------------------
// Fully fused SSN: init + 10 iterations + final outputs, one persistent kernel.
// One CTA per (b, cell); 256 threads. Cross-cell sync via per-cell flags
// (one post per contributing block); tree-reduced single-atomic publish.
// ---------------------------------------------------------------------------
__global__ __launch_bounds__(256, 4) void k_fused(const float* __restrict__ feats,
                                                  float* __restrict__ gamma_out,
                                                  float* __restrict__ recon_out) {
    __shared__ __align__(16) float s_sh[9][C];          // neighbor spix / later fm
    __shared__ float sn_sh[9];
    __shared__ int   cell_sh[9];
    __shared__ int   expect_sh[9];
    __shared__ __align__(16) float pix_sh[C * PITCH];
    __shared__ __align__(16) float aff_sh[9][256];      // aliased as s_acc in reduce

    int blk = blockIdx.x;
    int b = blk / J, j = blk % J;
    int jy = j / JW, jx = j % JW;
    int bJ = b * J;
    int t = threadIdx.x;
    int wk = t >> 5, lane = t & 31;

    // neighbor table + expected contributor counts (static)
    if (t < 9) {
        int dy = t / 3 - 1, dx = t % 3 - 1;
        int ny = jy + dy, nx = jx + dx;
        int nc = (ny >= 0 && ny < JH && nx >= 0 && nx < JW) ? ny * JW + nx : -1;
        cell_sh[t] = nc;
        int ex = 0;
        if (nc >= 0) {
            int cy = 3 - (ny == 0) - (ny == JH - 1);
            int cx = 3 - (nx == 0) - (nx == JW - 1);
            ex = cy * cx;
        }
        expect_sh[t] = ex;
    }

    // load pixel features ONCE into smem; compute |f|^2 (fn persists, 1 reg)
    int py = t >> 4, px = t & 15;
    int y = jy * 16 + py, x = jx * 16 + px;
    int n = y * W + x;
    const float* fp = feats + (size_t)b * C * HW + n;
    float fn;
    {
        unsigned long long fn2 = 0ull;
        #pragma unroll
        for (int i = 0; i < 16; i++) {
            float lo = fp[(2 * i) * HW];
            float hi = fp[(2 * i + 1) * HW];
            pix_sh[(2 * i) * PITCH + t]     = lo;
            pix_sh[(2 * i + 1) * PITCH + t] = hi;
            unsigned long long v = f2pack(lo, hi);
            ffma2(fn2, v, v);
        }
        fn = f2sum(fn2);
    }

    // zero own cell's slots 1..10; write slot-0 den
    if (t < C) {
        #pragma unroll
        for (int s = 1; s < SLOTS; s++) g_num[s][(bJ + j) * C + t] = 0.0f;
    }
    if (t == C) {
        #pragma unroll
        for (int s = 1; s < SLOTS; s++) g_den[s][bJ + j] = 0.0f;
        g_den[0][bJ + j] = 256.0f;   // so num/(den+eps) == cell mean exactly
    }
    __syncthreads();   // pix_sh + tables ready

    // slot-0 num = per-channel sum over own 16x16 cell (warp slices -> tree)
    {
        const float* pr = &pix_sh[lane * PITCH + wk * 32];
        float ms = 0.0f;
        #pragma unroll
        for (int i = 0; i < 32; i += 4) {
            float4 v = *(const float4*)&pr[i];
            ms += (v.x + v.y) + (v.z + v.w);
        }
        ((float*)aff_sh)[wk * 32 + lane] = ms;
        __syncthreads();
        if (wk == 0) {
            float s = 0.0f;
            #pragma unroll
            for (int w2 = 0; w2 < 8; w2++) s += ((float*)aff_sh)[w2 * 32 + lane];
            g_num[0][(bJ + j) * C + lane] = s;
        }
    }
    __threadfence();
    __syncthreads();
    if (t == 0) atomicAdd(&g_flag[0][bJ + j], 1u);   // publish slot 0 (expect 1)

    float a[9];               // own-pixel affinities (persist to finale)

    for (int it = 0; it < NITER; it++) {
        // ---- phase 0: joint-poll this warp's flags, then load neighbor spix ----
        {
            int k1 = wk, k2 = (wk == 0) ? 8 : -1;
            const unsigned* p1 = nullptr; unsigned e1 = 0;
            const unsigned* p2 = nullptr; unsigned e2 = 0;
            if (cell_sh[k1] >= 0) {
                p1 = &g_flag[it][bJ + cell_sh[k1]];
                e1 = (it == 0) ? 1u : (unsigned)expect_sh[k1];
            }
            if (k2 >= 0 && cell_sh[k2] >= 0) {
                p2 = &g_flag[it][bJ + cell_sh[k2]];
                e2 = (it == 0) ? 1u : (unsigned)expect_sh[k2];
            }
            poll_flag2(p1, e1, p2, e2);
        }
        for (int k = wk; k < 9; k += 8) {
            int nc = cell_sh[k];
            float sv = 0.0f;
            if (nc >= 0) {
                int idx = bJ + nc;
                sv = __ldcg(&g_num[it][idx * C + lane]) /
                     (__ldcg(&g_den[it][idx]) + 1e-16f);
            }
            s_sh[k][lane] = sv;
            float sq = sv * sv;
            #pragma unroll
            for (int o = 16; o; o >>= 1) sq += __shfl_xor_sync(0xffffffffu, sq, o);
            if (lane == 0) sn_sh[k] = sq;
        }
        __syncthreads();

        // ---- phase 1: distances (f32x2 FMA; f repacked from smem) + softmax ----
        unsigned long long d2[9];
        #pragma unroll
        for (int k = 0; k < 9; k++) d2[k] = 0ull;
        #pragma unroll
        for (int c4 = 0; c4 < 8; c4++) {
            float fa = pix_sh[(4 * c4 + 0) * PITCH + t];
            float fb = pix_sh[(4 * c4 + 1) * PITCH + t];
            float fc = pix_sh[(4 * c4 + 2) * PITCH + t];
            float fd = pix_sh[(4 * c4 + 3) * PITCH + t];
            unsigned long long fx = f2pack(fa, fb);
            unsigned long long fy = f2pack(fc, fd);
            #pragma unroll
            for (int k = 0; k < 9; k++) {
                ulonglong2 sv = ((const ulonglong2*)s_sh[k])[c4];
                ffma2(d2[k], fx, sv.x);
                ffma2(d2[k], fy, sv.y);
            }
        }
        float dist[9];
        #pragma unroll
        for (int k = 0; k < 9; k++)
            dist[k] = fn - 2.0f * f2sum(d2[k]) + sn_sh[k];

        float m = 3.0e38f;
        #pragma unroll
        for (int k = 0; k < 9; k++)
            if (cell_sh[k] >= 0) m = fminf(m, dist[k]);
        float sum = 0.0f;
        #pragma unroll
        for (int k = 0; k < 9; k++) {
            a[k] = (cell_sh[k] >= 0) ? __expf(m - dist[k]) : 0.0f;
            sum += a[k];
        }
        float inv = 1.0f / sum;
        #pragma unroll
        for (int k = 0; k < 9; k++) {
            a[k] *= inv;
            aff_sh[k][t] = a[k];
        }
        __syncthreads();

        // ---- phase 2: warp-slice accumulation (lane = channel), f32x2 ----
        unsigned long long acc2[9];
        #pragma unroll
        for (int k = 0; k < 9; k++) acc2[k] = 0ull;
        {
            int p0 = wk * 32;
            const float* pr = &pix_sh[lane * PITCH + p0];
            #pragma unroll
            for (int i = 0; i < 32; i += 4) {
                ulonglong2 pv = *(const ulonglong2*)&pr[i];
                #pragma unroll
                for (int k = 0; k < 9; k++) {
                    ulonglong2 av = *(const ulonglong2*)&aff_sh[k][p0 + i];  // bcast
                    ffma2(acc2[k], av.x, pv.x);
                    ffma2(acc2[k], av.y, pv.y);
                }
            }
        }
        // denominators (read aff_sh before it is aliased); lane 0 holds result
        float dreg[2] = {0.0f, 0.0f};
        {
            int nd = 0;
            for (int k = wk; k < 9; k += 8) {
                float d = 0.0f;
                #pragma unroll
                for (int i2 = 0; i2 < 8; i2++) d += aff_sh[k][lane + (i2 << 5)];
                #pragma unroll
                for (int o = 16; o; o >>= 1) d += __shfl_xor_sync(0xffffffffu, d, o);
                dreg[nd++] = d;
            }
        }
        __syncthreads();                       // aff_sh + pix_sh reads done
        if (it == NITER - 1) {                 // stash affinities for the finale
            #pragma unroll
            for (int k = 0; k < 9; k++) pix_sh[k * 256 + t] = a[k];
        }
        float* s_acc = (float*)aff_sh;         // [8][9][32]
        #pragma unroll
        for (int k = 0; k < 9; k++)
            s_acc[(wk * 9 + k) * 32 + lane] = f2sum(acc2[k]);
        __syncthreads();

        // ---- tree reduce + single atomic per (neighbor, channel) + flags ----
        {
            int nd = 0;
            for (int k = wk; k < 9; k += 8) {
                int nc = cell_sh[k];
                float dv = dreg[nd++];
                if (nc >= 0) {
                    float v = 0.0f;
                    #pragma unroll
                    for (int w2 = 0; w2 < 8; w2++)
                        v += s_acc[(w2 * 9 + k) * 32 + lane];
                    atomicAdd(&g_num[it + 1][(bJ + nc) * C + lane], v);
                    if (lane == 0) atomicAdd(&g_den[it + 1][bJ + nc], dv);
                }
            }
        }
        __threadfence();                       // warp-level: prior atomics visible
        for (int k = wk; k < 9; k += 8) {
            int nc = cell_sh[k];
            if (nc >= 0 && lane == 0) atomicAdd(&g_flag[it + 1][bJ + nc], 1u);
        }
    }

    // =======================================================================
    // Finale: gamma first (depends only on stashed aff), then fm + recon.
    // =======================================================================
    const float* aff2 = pix_sh;
    {
        int q = t & 63, jr = t >> 6;
        int r = q >> 2, colq = q & 3;
        size_t rowoff = (size_t)(jy * 16 + r) * W + jx * 16 + colq * 4;
        #pragma unroll 4
        for (int i = 0; i < 48; i++) {
            int jv  = jr + (i << 2);
            int jjy = jv >> 4, jjx = jv & 15;
            int ddy = jjy - jy, ddx = jjx - jx;
            float4 v = make_float4(0.f, 0.f, 0.f, 0.f);
            if (ddy >= -1 && ddy <= 1 && ddx >= -1 && ddx <= 1) {
                int k = (ddy + 1) * 3 + (ddx + 1);
                v = *(const float4*)&aff2[k * 256 + r * 16 + colq * 4];
            }
            __stcs((float4*)&gamma_out[((size_t)(bJ + jv)) * N + rowoff], v);
        }
    }

    // fm = num[10]/(den[10]+1e-6), gated on slot-10 flags (joint poll per warp)
    {
        int k1 = wk, k2 = (wk == 0) ? 8 : -1;
        const unsigned* p1 = nullptr; unsigned e1 = 0;
        const unsigned* p2 = nullptr; unsigned e2 = 0;
        if (cell_sh[k1] >= 0) {
            p1 = &g_flag[NITER][bJ + cell_sh[k1]];
            e1 = (unsigned)expect_sh[k1];
        }
        if (k2 >= 0 && cell_sh[k2] >= 0) {
            p2 = &g_flag[NITER][bJ + cell_sh[k2]];
            e2 = (unsigned)expect_sh[k2];
        }
        poll_flag2(p1, e1, p2, e2);
    }
    for (int k = wk; k < 9; k += 8) {
        int nc = cell_sh[k];
        float fv = 0.0f;
        if (nc >= 0) {
            int idx = bJ + nc;
            fv = __ldcg(&g_num[NITER][idx * C + lane]) /
                 (__ldcg(&g_den[NITER][idx]) + 1e-6f);
        }
        s_sh[k][lane] = fv;
    }
    __syncthreads();

    // recon[b,c,n] = sum_k a[k] * fm[cell_k][c]   (f32x2)
    unsigned long long rec2[16];
    #pragma unroll
    for (int i = 0; i < 16; i++) rec2[i] = 0ull;
    #pragma unroll
    for (int k = 0; k < 9; k++) {
        unsigned long long ak2 = f2pack(a[k], a[k]);
        const ulonglong2* s2 = (const ulonglong2*)s_sh[k];
        #pragma unroll
        for (int c4 = 0; c4 < 8; c4++) {
            ulonglong2 sv = s2[c4];
            ffma2(rec2[2 * c4],     ak2, sv.x);
            ffma2(rec2[2 * c4 + 1], ak2, sv.y);
        }
    }
    #pragma unroll
    for (int i = 0; i < 16; i++) {
        float lo, hi;
        f2unpack(rec2[i], lo, hi);
        __stcs(&recon_out[((size_t)(b * C + 2 * i) * H + y) * W + x], lo);
        __stcs(&recon_out[((size_t)(b * C + 2 * i + 1) * H + y) * W + x], hi);
    }
}

// ---------------------------------------------------------------------------
extern "C" void kernel_launch(void* const* d_in, const int* in_sizes, int n_in,
                              void* d_out, int out_size) {
    (void)in_sizes; (void)n_in; (void)out_size;
    const float* feats = (const float*)d_in[0];
    float* gamma = (float*)d_out;
    float* recon = gamma + (size_t)B * J * N;

    k_reset<<<(SLOTS * B * J + 255) / 256, 256>>>();
    k_fused<<<NB, 256>>>(feats, gamma, recon);
}